// round 1
// baseline (speedup 1.0000x reference)
#include <cuda_runtime.h>
#include <cuda_bf16.h>

#define BIG 1e9f
#define FULLMASK 0xFFFFFFFFu

// One warp per batch element. Each lane owns columns (2*lane, 2*lane+1) of the
// 64-wide grid. 63 sequential row steps; within each row a min-plus warp scan
// (associative combine over pairs (a, c): a' = a1+a2, c' = min(c2, c1+a2)).
__global__ void __launch_bounds__(128, 16) dp_shortest_path_kernel(
    const float* __restrict__ img, float* __restrict__ out, int B)
{
    const int warp_global = (blockIdx.x * blockDim.x + threadIdx.x) >> 5;
    const int lane = threadIdx.x & 31;
    if (warp_global >= B) return;

    const float2* row_ptr = reinterpret_cast<const float2*>(img + (size_t)warp_global * 64 * 64) + lane;

    // ---- Row 0: cumulative sum of right-edge weights -------------------
    float2 cur = __ldg(row_ptr);              // row 0, cols 2L, 2L+1
    float2 nxt = __ldg(row_ptr + 32);         // prefetch row 1

    float img_left = __shfl_up_sync(FULLMASK, cur.y, 1);     // img[0][2L-1]
    float a0 = (lane == 0) ? BIG : 0.5f * (img_left + cur.x);
    float a1 = 0.5f * (cur.x + cur.y);
    float c0 = (lane == 0) ? 0.0f : BIG;
    float c1 = BIG;

    float v0, v1;
    {
        // in-thread combine of the pair, then 5-step warp min-plus scan
        float A = a0 + a1;
        float C = fminf(c1, c0 + a1);
        #pragma unroll
        for (int off = 1; off < 32; off <<= 1) {
            float Ap = __shfl_up_sync(FULLMASK, A, off);
            float Cp = __shfl_up_sync(FULLMASK, C, off);
            if (lane >= off) {
                C = fminf(C, Cp + A);
                A = Ap + A;
            }
        }
        float Cexcl = __shfl_up_sync(FULLMASK, C, 1);   // v[2L-1]
        // a0 == BIG on lane 0 -> exclusive term can never win there
        v0 = fminf(c0, Cexcl + a0);
        v1 = C;                                          // v[2L+1]
    }

    float2 prev_img = cur;
    float pd0 = v0, pd1 = v1;

    // ---- Rows 1..63 ----------------------------------------------------
    #pragma unroll 1
    for (int i = 1; i < 64; i++) {
        cur = nxt;
        if (i < 63) nxt = __ldg(row_ptr + (i + 1) * 32);  // prefetch next row

        float img_prev_left = __shfl_up_sync(FULLMASK, prev_img.y, 1); // img[i-1][2L-1]
        float img_cur_left  = __shfl_up_sync(FULLMASK, cur.y, 1);      // img[i  ][2L-1]
        float pd_left       = __shfl_up_sync(FULLMASK, pd1, 1);        // d[i-1][2L-1]

        // down-edge candidates
        c0 = pd0 + 0.5f * (prev_img.x + cur.x);
        c1 = pd1 + 0.5f * (prev_img.y + cur.y);
        // diag-edge candidates
        if (lane > 0) {
            c0 = fminf(c0, pd_left + 0.5f * (img_prev_left + cur.x));
        }
        c1 = fminf(c1, pd0 + 0.5f * (prev_img.x + cur.y));
        // right-edge weights for this row
        a0 = (lane == 0) ? BIG : 0.5f * (img_cur_left + cur.x);
        a1 = 0.5f * (cur.x + cur.y);

        // min-plus scan along the row
        float A = a0 + a1;
        float C = fminf(c1, c0 + a1);
        #pragma unroll
        for (int off = 1; off < 32; off <<= 1) {
            float Ap = __shfl_up_sync(FULLMASK, A, off);
            float Cp = __shfl_up_sync(FULLMASK, C, off);
            if (lane >= off) {
                C = fminf(C, Cp + A);
                A = Ap + A;
            }
        }
        float Cexcl = __shfl_up_sync(FULLMASK, C, 1);
        v0 = fminf(c0, Cexcl + a0);
        v1 = C;

        pd0 = v0;
        pd1 = v1;
        prev_img = cur;
    }

    if (lane == 31) out[warp_global] = pd1;   // d[63][63]
}

extern "C" void kernel_launch(void* const* d_in, const int* in_sizes, int n_in,
                              void* d_out, int out_size) {
    const float* img = (const float*)d_in[0];
    float* out = (float*)d_out;
    int B = in_sizes[0] / (64 * 64);
    int threads = 128;                 // 4 warps per block
    int blocks = (B * 32 + threads - 1) / threads;
    dp_shortest_path_kernel<<<blocks, threads>>>(img, out, B);
}